// round 2
// baseline (speedup 1.0000x reference)
#include <cuda_runtime.h>
#include <cuda_bf16.h>
#include <math.h>

#define RB 4
#define CC 256
#define HH 64
#define WW 64
#define HWSZ 4096
#define KK 9
#define OC2 18
#define CKSZ 2304   // C*K

// ---------------- scratch (device globals; no allocations allowed) ----------
__device__ float g_bufA[RB * CC * HH * WW / 1];       // 4*256*64*64 = 4194304
__device__ float g_bufB[4194304];
__device__ float g_off[4 * OC2 * HH * WW];            // 294912
__device__ float g_wt[RB * CKSZ * CC];                // 9437184 (transposed weights)

// ---------------- weight transpose: w[r][oc][c][kh][kw] -> wt[r][c*9+k][oc] --
__global__ void transpose_w_kernel(const float* __restrict__ w, float* __restrict__ wt) {
    int idx = blockIdx.x * blockDim.x + threadIdx.x;
    if (idx >= RB * CKSZ * CC) return;
    int oc = idx & 255;
    int ck = (idx >> 8) % CKSZ;
    int r  = idx / (CKSZ * 256);
    int c = ck / 9, k = ck % 9;
    wt[idx] = w[(((r * 256 + oc) * 256 + c) * 9) + k];
}

// ---------------- offset conv: 3x3, C=256 -> 18, pad 1 ----------------------
// grid = B*H (256 blocks), block = 256 threads = 64 w  x  4 channel-groups(64 ch each)
__global__ __launch_bounds__(256) void offset_conv_kernel(
    const float* __restrict__ x, const float* __restrict__ offw,
    const float* __restrict__ offb, float* __restrict__ off)
{
    __shared__ float xs[6336];   // [cgci(32)][rr(3)][wc(66)]
    __shared__ float ws[5184];   // [cgci(32)][oc(18)][t(9)]
    int b = blockIdx.x >> 6;
    int h = blockIdx.x & 63;
    int tid = threadIdx.x;
    int wp = tid & 63;
    int cg = tid >> 6;           // 0..3

    float acc[18];
#pragma unroll
    for (int o = 0; o < 18; ++o) acc[o] = 0.f;

    for (int chunk = 0; chunk < 8; ++chunk) {
        // stage x tile: channels [cg*64 + chunk*8 .. +7] for all 4 cgs, rows h-1..h+1, cols -1..64
        for (int i = tid; i < 6336; i += 256) {
            int wc = i % 66;
            int rr = (i / 66) % 3;
            int cgci = i / 198;                     // 0..31
            int c = ((cgci >> 3) << 6) + (chunk << 3) + (cgci & 7);
            int hh = h - 1 + rr;
            int ww2 = wc - 1;
            float v = 0.f;
            if (hh >= 0 && hh < 64 && ww2 >= 0 && ww2 < 64)
                v = x[((b * CC + c) * 64 + hh) * 64 + ww2];
            xs[i] = v;
        }
        // stage weights
        for (int i = tid; i < 5184; i += 256) {
            int t = i % 9;
            int oc = (i / 9) % 18;
            int cgci = i / 162;
            int c = ((cgci >> 3) << 6) + (chunk << 3) + (cgci & 7);
            ws[i] = offw[(oc * CC + c) * 9 + t];
        }
        __syncthreads();

#pragma unroll
        for (int ci = 0; ci < 8; ++ci) {
            int cgci = (cg << 3) + ci;
            float patch[9];
#pragma unroll
            for (int rr = 0; rr < 3; ++rr)
#pragma unroll
                for (int kw = 0; kw < 3; ++kw)
                    patch[rr * 3 + kw] = xs[(cgci * 3 + rr) * 66 + wp + kw];
            const float* wrow = &ws[cgci * 162];
#pragma unroll
            for (int oc = 0; oc < 18; ++oc) {
                float a = acc[oc];
#pragma unroll
                for (int t = 0; t < 9; ++t) a = fmaf(patch[t], wrow[oc * 9 + t], a);
                acc[oc] = a;
            }
        }
        __syncthreads();
    }

    // 4-way cross-channel-group reduction (reuse xs region)
    float* red = xs;  // needs 4*64*18 = 4608 floats
#pragma unroll
    for (int oc = 0; oc < 18; ++oc)
        red[((cg << 6) + wp) * 18 + oc] = acc[oc];
    __syncthreads();
    for (int i = tid; i < 1152; i += 256) {
        int oc = i >> 6;
        int wq = i & 63;
        float s = red[wq * 18 + oc] + red[(64 + wq) * 18 + oc]
                + red[(128 + wq) * 18 + oc] + red[(192 + wq) * 18 + oc] + offb[oc];
        off[((b * OC2 + oc) * 64 + h) * 64 + wq] = s;
    }
}

// ---------------- deform conv + relu --------------------------------------
// grid = 1024 blocks (b,h,wtile of 16 pixels), block = 256 threads
// threads = 128 oc-pairs x 2 pixel-groups(8 px each)
__global__ __launch_bounds__(256) void deform_conv_kernel(
    const float* __restrict__ x, const float* __restrict__ off,
    const float* __restrict__ wt, float* __restrict__ out)
{
    __shared__ int   sIdx[576];       // [p(16)][k(9)][4 corners]
    __shared__ float sWgt[576];
    __shared__ float s[2304];         // sampled [ck(144)][p(16)]
    __shared__ float sout[4096];      // [oc(256)][p(16)]

    int blk = blockIdx.x;
    int b  = blk >> 8;
    int h  = (blk >> 2) & 63;
    int w0 = (blk & 3) << 4;
    int tid = threadIdx.x;

    // ---- sampling metadata (per pixel, per tap) ----
    if (tid < 144) {
        int p = tid / 9, k = tid % 9;
        int wq = w0 + p;
        float dy = off[((b * OC2 + 2 * k) * 64 + h) * 64 + wq];
        float dx = off[((b * OC2 + 2 * k + 1) * 64 + h) * 64 + wq];
        float py = (float)(h + k / 3 - 1) + dy;
        float px = (float)(wq + k % 3 - 1) + dx;
        float y0f = floorf(py), x0f = floorf(px);
        int y0 = (int)y0f, x0 = (int)x0f;
        float wy = py - y0f, wx = px - x0f;
        float cw[4];
        int cy[4], cx[4];
        cw[0] = (1.f - wy) * (1.f - wx); cy[0] = y0;     cx[0] = x0;
        cw[1] = (1.f - wy) * wx;         cy[1] = y0;     cx[1] = x0 + 1;
        cw[2] = wy * (1.f - wx);         cy[2] = y0 + 1; cx[2] = x0;
        cw[3] = wy * wx;                 cy[3] = y0 + 1; cx[3] = x0 + 1;
        int base4 = tid * 4;
#pragma unroll
        for (int q = 0; q < 4; ++q) {
            bool valid = (cy[q] >= 0) && (cy[q] < 64) && (cx[q] >= 0) && (cx[q] < 64);
            int yy = cy[q] < 0 ? 0 : (cy[q] > 63 ? 63 : cy[q]);
            int xx = cx[q] < 0 ? 0 : (cx[q] > 63 ? 63 : cx[q]);
            sIdx[base4 + q] = yy * 64 + xx;
            sWgt[base4 + q] = valid ? cw[q] : 0.f;
        }
    }
    __syncthreads();

    float acc[16];
#pragma unroll
    for (int i = 0; i < 16; ++i) acc[i] = 0.f;

    int pg  = tid >> 7;    // pixel group 0/1
    int ocp = tid & 127;   // oc pair index
    const float* xb = x + (size_t)b * CC * HWSZ;
    const float4* s4 = (const float4*)s;

    for (int chunk = 0; chunk < 16; ++chunk) {
        int c0 = chunk << 4;
        // ---- stage sampled values: s[(cc*9+k)*16 + p] ----
#pragma unroll
        for (int i = 0; i < 9; ++i) {
            int j = tid + (i << 8);
            int p  = j & 15;
            int ck = j >> 4;            // cc*9 + k
            int cc = ck / 9;
            int k  = ck - cc * 9;
            int mi = (p * 9 + k) << 2;
            const float* xp = xb + (size_t)(c0 + cc) * HWSZ;
            float v;
            v = sWgt[mi]     * xp[sIdx[mi]];
            v = fmaf(sWgt[mi + 1], xp[sIdx[mi + 1]], v);
            v = fmaf(sWgt[mi + 2], xp[sIdx[mi + 2]], v);
            v = fmaf(sWgt[mi + 3], xp[sIdx[mi + 3]], v);
            s[j] = v;
        }
        __syncthreads();

        // ---- inner product: 144 ck rows, 2 oc x 8 px per thread ----
        const float2* wrow = (const float2*)(wt + (size_t)(c0 * 9) * 256) + ocp;
#pragma unroll 8
        for (int jj = 0; jj < 144; ++jj) {
            float2 wv = wrow[jj * 128];
            float4 sa = s4[jj * 4 + pg * 2];
            float4 sb = s4[jj * 4 + pg * 2 + 1];
            acc[0]  = fmaf(sa.x, wv.x, acc[0]);
            acc[1]  = fmaf(sa.y, wv.x, acc[1]);
            acc[2]  = fmaf(sa.z, wv.x, acc[2]);
            acc[3]  = fmaf(sa.w, wv.x, acc[3]);
            acc[4]  = fmaf(sb.x, wv.x, acc[4]);
            acc[5]  = fmaf(sb.y, wv.x, acc[5]);
            acc[6]  = fmaf(sb.z, wv.x, acc[6]);
            acc[7]  = fmaf(sb.w, wv.x, acc[7]);
            acc[8]  = fmaf(sa.x, wv.y, acc[8]);
            acc[9]  = fmaf(sa.y, wv.y, acc[9]);
            acc[10] = fmaf(sa.z, wv.y, acc[10]);
            acc[11] = fmaf(sa.w, wv.y, acc[11]);
            acc[12] = fmaf(sb.x, wv.y, acc[12]);
            acc[13] = fmaf(sb.y, wv.y, acc[13]);
            acc[14] = fmaf(sb.z, wv.y, acc[14]);
            acc[15] = fmaf(sb.w, wv.y, acc[15]);
        }
        __syncthreads();
    }

    // ---- epilogue: relu, stage to smem, coalesced store ----
#pragma unroll
    for (int q = 0; q < 2; ++q)
#pragma unroll
        for (int pp = 0; pp < 8; ++pp) {
            float v = acc[q * 8 + pp];
            v = v > 0.f ? v : 0.f;
            sout[(2 * ocp + q) * 16 + pg * 8 + pp] = v;
        }
    __syncthreads();
    float* outb = out + (size_t)b * CC * HWSZ + h * 64 + w0;
    for (int i = tid; i < 4096; i += 256) {
        int oc = i >> 4, p = i & 15;
        outb[(size_t)oc * HWSZ + p] = sout[i];
    }
}

// ---------------- launch ----------------------------------------------------
extern "C" void kernel_launch(void* const* d_in, const int* in_sizes, int n_in,
                              void* d_out, int out_size) {
    (void)in_sizes; (void)n_in; (void)out_size;
    const float* x    = (const float*)d_in[0];
    const float* offw = (const float*)d_in[1];
    const float* offb = (const float*)d_in[2];
    const float* w    = (const float*)d_in[3];
    float* out = (float*)d_out;

    float *bufA, *bufB, *goff, *gwt;
    cudaGetSymbolAddress((void**)&bufA, g_bufA);
    cudaGetSymbolAddress((void**)&bufB, g_bufB);
    cudaGetSymbolAddress((void**)&goff, g_off);
    cudaGetSymbolAddress((void**)&gwt,  g_wt);

    transpose_w_kernel<<<(RB * CKSZ * CC + 255) / 256, 256>>>(w, gwt);

    const float* cur = x;
    for (int r = 0; r < RB; ++r) {
        float* nxt = (r == 3) ? out : ((r & 1) == 0 ? bufA : bufB);
        offset_conv_kernel<<<256, 256>>>(cur, offw + (size_t)r * OC2 * CC * 9,
                                         offb + r * OC2, goff);
        deform_conv_kernel<<<1024, 256>>>(cur, goff, gwt + (size_t)r * CKSZ * CC, nxt);
        cur = nxt;
    }
}

// round 4
// speedup vs baseline: 2.7242x; 2.7242x over previous
#include <cuda_runtime.h>
#include <cuda_bf16.h>
#include <math.h>
#include <stdint.h>

#define RB 4
#define CC 256
#define HWSZ 4096
#define OC2 18

// ---------------- smem layout for deform_mma (bytes, dynamic) ---------------
#define SM_A     0                      // A_hi [256 oc][64 ck] bf16 = 32768
#define SM_ALO   32768                  // A_lo
#define SM_BHI   65536                  // B_hi [128 px][64 ck] bf16 = 16384
#define SM_BLO   81920
#define SM_MIDX  98304                  // int   [9][128][4] = 18432
#define SM_MW    116736                 // float [9][128][4] = 18432
#define SM_TOTAL 135168

// ---------------- scratch (device globals; no allocations allowed) ----------
__device__ float g_bufA[4194304];
__device__ float g_bufB[4194304];
__device__ float g_off[294912];
// weights reordered: [r][kb=kk*4+cb (36)][oc (256)][j (64)] with c = cb*64+j
__device__ __align__(16) __nv_bfloat16 g_whi[2359296];
__device__ __align__(16) __nv_bfloat16 g_wlo[2359296];

// ---------------- PTX helpers ----------------------------------------------
static __device__ __forceinline__ uint32_t smem_u32(const void* p) {
    uint32_t a;
    asm("{ .reg .u64 t; cvta.to.shared.u64 t, %1; cvt.u32.u64 %0, t; }" : "=r"(a) : "l"(p));
    return a;
}

#define LDSM4(r, a) \
    asm volatile("ldmatrix.sync.aligned.m8n8.x4.shared.b16 {%0,%1,%2,%3}, [%4];" \
                 : "=r"((r)[0]), "=r"((r)[1]), "=r"((r)[2]), "=r"((r)[3]) : "r"(a))

#define MMA16816(c, a, b0, b1) \
    asm volatile("mma.sync.aligned.m16n8k16.row.col.f32.bf16.bf16.f32 " \
                 "{%0,%1,%2,%3}, {%4,%5,%6,%7}, {%8,%9}, {%0,%1,%2,%3};" \
                 : "+f"((c)[0]), "+f"((c)[1]), "+f"((c)[2]), "+f"((c)[3]) \
                 : "r"((a)[0]), "r"((a)[1]), "r"((a)[2]), "r"((a)[3]), \
                   "r"(b0), "r"(b1))

// ---------------- weight prep: fp32 -> bf16 hi/lo, reordered ----------------
__global__ void prep_w_kernel(const float* __restrict__ w,
                              __nv_bfloat16* __restrict__ whi,
                              __nv_bfloat16* __restrict__ wlo) {
    int idx = blockIdx.x * 256 + threadIdx.x;
    if (idx >= 2359296) return;
    int r = idx / 589824;
    int rem = idx - r * 589824;
    int kb = rem >> 14;
    int rem2 = rem & 16383;
    int oc = rem2 >> 6;
    int j = rem2 & 63;
    int kk = kb >> 2;
    int c = ((kb & 3) << 6) + j;
    float v = w[(((r * 256 + oc) * 256 + c) * 9) + kk];
    __nv_bfloat16 h = __float2bfloat16_rn(v);
    whi[idx] = h;
    wlo[idx] = __float2bfloat16_rn(v - __bfloat162float(h));
}

// ---------------- offset conv: 3x3, C=256 -> 18, pad 1 (unchanged) ----------
__global__ __launch_bounds__(256) void offset_conv_kernel(
    const float* __restrict__ x, const float* __restrict__ offw,
    const float* __restrict__ offb, float* __restrict__ off)
{
    __shared__ float xs[6336];
    __shared__ float ws[5184];
    int b = blockIdx.x >> 6;
    int h = blockIdx.x & 63;
    int tid = threadIdx.x;
    int wp = tid & 63;
    int cg = tid >> 6;

    float acc[18];
#pragma unroll
    for (int o = 0; o < 18; ++o) acc[o] = 0.f;

    for (int chunk = 0; chunk < 8; ++chunk) {
        for (int i = tid; i < 6336; i += 256) {
            int wc = i % 66;
            int rr = (i / 66) % 3;
            int cgci = i / 198;
            int c = ((cgci >> 3) << 6) + (chunk << 3) + (cgci & 7);
            int hh = h - 1 + rr;
            int ww2 = wc - 1;
            float v = 0.f;
            if (hh >= 0 && hh < 64 && ww2 >= 0 && ww2 < 64)
                v = x[((b * CC + c) * 64 + hh) * 64 + ww2];
            xs[i] = v;
        }
        for (int i = tid; i < 5184; i += 256) {
            int t = i % 9;
            int oc = (i / 9) % 18;
            int cgci = i / 162;
            int c = ((cgci >> 3) << 6) + (chunk << 3) + (cgci & 7);
            ws[i] = offw[(oc * CC + c) * 9 + t];
        }
        __syncthreads();

#pragma unroll
        for (int ci = 0; ci < 8; ++ci) {
            int cgci = (cg << 3) + ci;
            float patch[9];
#pragma unroll
            for (int rr = 0; rr < 3; ++rr)
#pragma unroll
                for (int kw = 0; kw < 3; ++kw)
                    patch[rr * 3 + kw] = xs[(cgci * 3 + rr) * 66 + wp + kw];
            const float* wrow = &ws[cgci * 162];
#pragma unroll
            for (int oc = 0; oc < 18; ++oc) {
                float a = acc[oc];
#pragma unroll
                for (int t = 0; t < 9; ++t) a = fmaf(patch[t], wrow[oc * 9 + t], a);
                acc[oc] = a;
            }
        }
        __syncthreads();
    }

    float* red = xs;
#pragma unroll
    for (int oc = 0; oc < 18; ++oc)
        red[((cg << 6) + wp) * 18 + oc] = acc[oc];
    __syncthreads();
    for (int i = tid; i < 1152; i += 256) {
        int oc = i >> 6;
        int wq = i & 63;
        float s = red[wq * 18 + oc] + red[(64 + wq) * 18 + oc]
                + red[(128 + wq) * 18 + oc] + red[(192 + wq) * 18 + oc] + offb[oc];
        off[((b * OC2 + oc) * 64 + h) * 64 + wq] = s;
    }
}

// ---------------- deform conv via mma.sync (split-bf16, 3 combos) -----------
// grid = 128 CTAs (4 batches x 32 px-tiles of 128), 512 threads / 16 warps.
// CTA tile: D[256 oc][128 px]; warp tile 64x32 (4M x 4N warps).
__global__ __launch_bounds__(512, 1) void deform_mma_kernel(
    const float* __restrict__ x, const float* __restrict__ off,
    const __nv_bfloat16* __restrict__ whi, const __nv_bfloat16* __restrict__ wlo,
    float* __restrict__ out)
{
    extern __shared__ char smem[];
    uint32_t sb = smem_u32(smem);
    int tid = threadIdx.x;
    int lane = tid & 31;
    int wid = tid >> 5;
    int b = blockIdx.x >> 5;
    int px0 = (blockIdx.x & 31) << 7;

    int* midx = (int*)(smem + SM_MIDX);
    float* mwgt = (float*)(smem + SM_MW);

    // ---- bilinear metadata: 9 taps x 128 pixels x 4 corners ----
    for (int i = tid; i < 1152; i += 512) {
        int kk = i >> 7;
        int p = i & 127;
        int pix = px0 + p;
        int h = pix >> 6;
        int w = pix & 63;
        float dy = off[((b * OC2 + 2 * kk) * 64 + h) * 64 + w];
        float dx = off[((b * OC2 + 2 * kk + 1) * 64 + h) * 64 + w];
        float py = (float)(h + kk / 3 - 1) + dy;
        float px_ = (float)(w + kk % 3 - 1) + dx;
        float y0f = floorf(py), x0f = floorf(px_);
        int y0 = (int)y0f, x0 = (int)x0f;
        float wy = py - y0f, wx = px_ - x0f;
        float cw[4];
        int cy[4], cx[4];
        cw[0] = (1.f - wy) * (1.f - wx); cy[0] = y0;     cx[0] = x0;
        cw[1] = (1.f - wy) * wx;         cy[1] = y0;     cx[1] = x0 + 1;
        cw[2] = wy * (1.f - wx);         cy[2] = y0 + 1; cx[2] = x0;
        cw[3] = wy * wx;                 cy[3] = y0 + 1; cx[3] = x0 + 1;
#pragma unroll
        for (int q = 0; q < 4; ++q) {
            bool valid = (cy[q] >= 0) && (cy[q] < 64) && (cx[q] >= 0) && (cx[q] < 64);
            int yy = cy[q] < 0 ? 0 : (cy[q] > 63 ? 63 : cy[q]);
            int xx = cx[q] < 0 ? 0 : (cx[q] > 63 ? 63 : cx[q]);
            midx[i * 4 + q] = yy * 64 + xx;
            mwgt[i * 4 + q] = valid ? cw[q] : 0.f;
        }
    }
    __syncthreads();

    float acc[4][4][4];
#pragma unroll
    for (int mi = 0; mi < 4; ++mi)
#pragma unroll
        for (int nj = 0; nj < 4; ++nj)
#pragma unroll
            for (int q = 0; q < 4; ++q) acc[mi][nj][q] = 0.f;

    int m_base = (wid & 3) << 6;
    int n_base = (wid >> 2) << 5;
    int px = tid & 127;
    int cg = tid >> 7;

    for (int kb = 0; kb < 36; ++kb) {
        int kk = kb >> 2;
        if (kb) __syncthreads();   // prior mma done before overwriting smem

        // ---- stage A (weights) hi/lo: swizzled [oc][64ck] ----
        {
            const uint4* ah = (const uint4*)(whi + ((size_t)kb << 14));
            const uint4* al = (const uint4*)(wlo + ((size_t)kb << 14));
#pragma unroll
            for (int t = 0; t < 4; ++t) {
                int i = tid + (t << 9);
                int row = i >> 3, seg = i & 7;
                uint32_t o = ((uint32_t)row << 7) + (((uint32_t)seg << 4) ^ ((row & 7) << 4));
                *(uint4*)(smem + SM_A + o) = ah[i];
                *(uint4*)(smem + SM_ALO + o) = al[i];
            }
        }

        // ---- sample B tile: [128 px][64 ck] tap kk, 16 channels/thread ----
        {
            const int* mi_ = &midx[(kk * 128 + px) * 4];
            const float* mw_ = &mwgt[(kk * 128 + px) * 4];
            int i0 = mi_[0], i1 = mi_[1], i2 = mi_[2], i3 = mi_[3];
            float w0 = mw_[0], w1 = mw_[1], w2 = mw_[2], w3 = mw_[3];
            const float* xb = x + ((size_t)(b * 256) + ((kb & 3) << 6) + (cg << 4)) * HWSZ;
            uint32_t hp[8], lp[8];
#pragma unroll
            for (int jj = 0; jj < 8; ++jj) {
                const float* p0 = xb + (size_t)(jj << 1) * HWSZ;
                const float* p1 = p0 + HWSZ;
                float v0 = fmaf(w3, p0[i3], fmaf(w2, p0[i2], fmaf(w1, p0[i1], w0 * p0[i0])));
                float v1 = fmaf(w3, p1[i3], fmaf(w2, p1[i2], fmaf(w1, p1[i1], w0 * p1[i0])));
                __nv_bfloat162 h2, l2;
                h2.x = __float2bfloat16_rn(v0);
                h2.y = __float2bfloat16_rn(v1);
                l2.x = __float2bfloat16_rn(v0 - __bfloat162float(h2.x));
                l2.y = __float2bfloat16_rn(v1 - __bfloat162float(h2.y));
                hp[jj] = *(uint32_t*)&h2;
                lp[jj] = *(uint32_t*)&l2;
            }
            uint32_t rb = (uint32_t)px << 7;
            uint32_t xm = ((uint32_t)px & 7) << 4;
            uint32_t c0b = (uint32_t)cg << 5;
            uint32_t o0 = rb + (c0b ^ xm);
            uint32_t o1 = rb + ((c0b + 16) ^ xm);
            *(uint4*)(smem + SM_BHI + o0) = make_uint4(hp[0], hp[1], hp[2], hp[3]);
            *(uint4*)(smem + SM_BHI + o1) = make_uint4(hp[4], hp[5], hp[6], hp[7]);
            *(uint4*)(smem + SM_BLO + o0) = make_uint4(lp[0], lp[1], lp[2], lp[3]);
            *(uint4*)(smem + SM_BLO + o1) = make_uint4(lp[4], lp[5], lp[6], lp[7]);
        }
        __syncthreads();

        // ---- ldmatrix + mma: 4 k16-steps ----
#pragma unroll
        for (int ks = 0; ks < 4; ++ks) {
            uint32_t ah_[4][4], al_[4][4], bf[2][4];
            int arow0 = m_base + (lane & 15);
            uint32_t acolb = (uint32_t)((ks << 5) + ((lane >> 4) << 4));
#pragma unroll
            for (int mi = 0; mi < 4; ++mi) {
                int row = arow0 + (mi << 4);
                uint32_t o = ((uint32_t)row << 7) + (acolb ^ ((row & 7) << 4));
                LDSM4(ah_[mi], sb + SM_A + o);
                LDSM4(al_[mi], sb + SM_ALO + o);
            }
            int brow0 = n_base + ((lane >> 4) << 3) + (lane & 7);
            uint32_t bcolb = (uint32_t)((ks << 5) + (((lane >> 3) & 1) << 4));
#pragma unroll
            for (int np = 0; np < 2; ++np) {
                int row = brow0 + (np << 4);
                uint32_t o = ((uint32_t)row << 7) + (bcolb ^ ((row & 7) << 4));
                LDSM4(bf[np], sb + SM_BHI + o);
            }
#pragma unroll
            for (int mi = 0; mi < 4; ++mi)
#pragma unroll
                for (int nj = 0; nj < 4; ++nj) {
                    MMA16816(acc[mi][nj], ah_[mi], bf[nj >> 1][(nj & 1) * 2], bf[nj >> 1][(nj & 1) * 2 + 1]);
                    MMA16816(acc[mi][nj], al_[mi], bf[nj >> 1][(nj & 1) * 2], bf[nj >> 1][(nj & 1) * 2 + 1]);
                }
#pragma unroll
            for (int np = 0; np < 2; ++np) {
                int row = brow0 + (np << 4);
                uint32_t o = ((uint32_t)row << 7) + (bcolb ^ ((row & 7) << 4));
                LDSM4(bf[np], sb + SM_BLO + o);
            }
#pragma unroll
            for (int mi = 0; mi < 4; ++mi)
#pragma unroll
                for (int nj = 0; nj < 4; ++nj)
                    MMA16816(acc[mi][nj], ah_[mi], bf[nj >> 1][(nj & 1) * 2], bf[nj >> 1][(nj & 1) * 2 + 1]);
        }
    }

    // ---- epilogue: relu + direct v2 stores ----
    float* outb = out + (size_t)b * CC * HWSZ + px0;
#pragma unroll
    for (int mi = 0; mi < 4; ++mi) {
#pragma unroll
        for (int nj = 0; nj < 4; ++nj) {
            int row = m_base + (mi << 4) + (lane >> 2);
            int colp = n_base + (nj << 3) + ((lane & 3) << 1);
            float2 v0, v1;
            v0.x = fmaxf(acc[mi][nj][0], 0.f);
            v0.y = fmaxf(acc[mi][nj][1], 0.f);
            v1.x = fmaxf(acc[mi][nj][2], 0.f);
            v1.y = fmaxf(acc[mi][nj][3], 0.f);
            *(float2*)(outb + (size_t)row * HWSZ + colp) = v0;
            *(float2*)(outb + (size_t)(row + 8) * HWSZ + colp) = v1;
        }
    }
}

// ---------------- launch ----------------------------------------------------
extern "C" void kernel_launch(void* const* d_in, const int* in_sizes, int n_in,
                              void* d_out, int out_size) {
    (void)in_sizes; (void)n_in; (void)out_size;
    const float* x    = (const float*)d_in[0];
    const float* offw = (const float*)d_in[1];
    const float* offb = (const float*)d_in[2];
    const float* w    = (const float*)d_in[3];
    float* out = (float*)d_out;

    float *bufA, *bufB, *goff;
    __nv_bfloat16 *gwhi, *gwlo;
    cudaGetSymbolAddress((void**)&bufA, g_bufA);
    cudaGetSymbolAddress((void**)&bufB, g_bufB);
    cudaGetSymbolAddress((void**)&goff, g_off);
    cudaGetSymbolAddress((void**)&gwhi, g_whi);
    cudaGetSymbolAddress((void**)&gwlo, g_wlo);

    cudaFuncSetAttribute(deform_mma_kernel,
                         cudaFuncAttributeMaxDynamicSharedMemorySize, SM_TOTAL);

    prep_w_kernel<<<(2359296 + 255) / 256, 256>>>(w, gwhi, gwlo);

    const float* cur = x;
    for (int r = 0; r < RB; ++r) {
        float* nxt = (r == 3) ? out : ((r & 1) == 0 ? bufA : bufB);
        offset_conv_kernel<<<256, 256>>>(cur, offw + (size_t)r * OC2 * CC * 9,
                                         offb + r * OC2, goff);
        deform_mma_kernel<<<128, 512, SM_TOTAL>>>(cur, goff, gwhi + (size_t)r * 589824,
                                                  gwlo + (size_t)r * 589824, nxt);
        cur = nxt;
    }
}

// round 5
// speedup vs baseline: 3.4182x; 1.2547x over previous
#include <cuda_runtime.h>
#include <cuda_bf16.h>
#include <math.h>
#include <stdint.h>

#define RB 4
#define CC 256
#define HWSZ 4096
#define OC2 18

// ---------------- smem layout (bytes, dynamic) ------------------------------
#define SM_A     0                      // A_hi [256 oc][64 ck] bf16 = 32768 (phase1: 32x64 = 4KB)
#define SM_ALO   32768                  // A_lo
#define SM_BHI   65536                  // B_hi [128 px][64 ck] bf16 = 16384 ; phase1 offs result [32][128] f32
#define SM_BLO   81920
#define SM_MIDX  98304                  // int   [9][128][4] = 18432
#define SM_MW    116736                 // float [9][128][4] = 18432
#define SM_TOTAL 135168

// ---------------- scratch (device globals; no allocations allowed) ----------
__device__ float g_bufA[4194304];
__device__ float g_bufB[4194304];
// main weights reordered: [r][kb=kk*4+cb (36)][oc (256)][j (64)], c = cb*64+j
__device__ __align__(16) __nv_bfloat16 g_whi[2359296];
__device__ __align__(16) __nv_bfloat16 g_wlo[2359296];
// offset-conv weights reordered: [r][kb (36)][ocp (32, pad from 18)][j (64)]
__device__ __align__(16) __nv_bfloat16 g_owhi[294912];
__device__ __align__(16) __nv_bfloat16 g_owlo[294912];

// ---------------- PTX helpers ----------------------------------------------
static __device__ __forceinline__ uint32_t smem_u32(const void* p) {
    uint32_t a;
    asm("{ .reg .u64 t; cvta.to.shared.u64 t, %1; cvt.u32.u64 %0, t; }" : "=r"(a) : "l"(p));
    return a;
}

#define LDSM4(r, a) \
    asm volatile("ldmatrix.sync.aligned.m8n8.x4.shared.b16 {%0,%1,%2,%3}, [%4];" \
                 : "=r"((r)[0]), "=r"((r)[1]), "=r"((r)[2]), "=r"((r)[3]) : "r"(a))

#define LDSM2(r, a) \
    asm volatile("ldmatrix.sync.aligned.m8n8.x2.shared.b16 {%0,%1}, [%2];" \
                 : "=r"((r)[0]), "=r"((r)[1]) : "r"(a))

#define MMA16816(c, a, b0, b1) \
    asm volatile("mma.sync.aligned.m16n8k16.row.col.f32.bf16.bf16.f32 " \
                 "{%0,%1,%2,%3}, {%4,%5,%6,%7}, {%8,%9}, {%0,%1,%2,%3};" \
                 : "+f"((c)[0]), "+f"((c)[1]), "+f"((c)[2]), "+f"((c)[3]) \
                 : "r"((a)[0]), "r"((a)[1]), "r"((a)[2]), "r"((a)[3]), \
                   "r"(b0), "r"(b1))

// ---------------- weight prep: fp32 -> bf16 hi/lo, reordered ----------------
__global__ void prep_w_kernel(const float* __restrict__ w,
                              __nv_bfloat16* __restrict__ whi,
                              __nv_bfloat16* __restrict__ wlo) {
    int idx = blockIdx.x * 256 + threadIdx.x;
    if (idx >= 2359296) return;
    int r = idx / 589824;
    int rem = idx - r * 589824;
    int kb = rem >> 14;
    int rem2 = rem & 16383;
    int oc = rem2 >> 6;
    int j = rem2 & 63;
    int kk = kb >> 2;
    int c = ((kb & 3) << 6) + j;
    float v = w[(((r * 256 + oc) * 256 + c) * 9) + kk];
    __nv_bfloat16 h = __float2bfloat16_rn(v);
    whi[idx] = h;
    wlo[idx] = __float2bfloat16_rn(v - __bfloat162float(h));
}

__global__ void prep_offw_kernel(const float* __restrict__ offw,
                                 __nv_bfloat16* __restrict__ owhi,
                                 __nv_bfloat16* __restrict__ owlo) {
    int idx = blockIdx.x * 256 + threadIdx.x;
    if (idx >= 294912) return;
    int r = idx / 73728;
    int rem = idx - r * 73728;
    int kb = rem >> 11;
    int rem2 = rem & 2047;
    int ocp = rem2 >> 6;
    int j = rem2 & 63;
    int kk = kb >> 2;
    int c = ((kb & 3) << 6) + j;
    float v = (ocp < OC2) ? offw[((r * OC2 + ocp) * 256 + c) * 9 + kk] : 0.f;
    __nv_bfloat16 h = __float2bfloat16_rn(v);
    owhi[idx] = h;
    owlo[idx] = __float2bfloat16_rn(v - __bfloat162float(h));
}

// ---------------- fused layer: offset conv GEMM + deform GEMM ---------------
// grid = 128 CTAs (4 batches x 32 px-tiles of 128), 512 threads / 16 warps.
__global__ __launch_bounds__(512, 1) void fused_layer_kernel(
    const float* __restrict__ x,
    const __nv_bfloat16* __restrict__ owhi, const __nv_bfloat16* __restrict__ owlo,
    const float* __restrict__ offbias,
    const __nv_bfloat16* __restrict__ whi, const __nv_bfloat16* __restrict__ wlo,
    float* __restrict__ out)
{
    extern __shared__ char smem[];
    uint32_t sb = smem_u32(smem);
    int tid = threadIdx.x;
    int lane = tid & 31;
    int wid = tid >> 5;
    int b = blockIdx.x >> 5;
    int px0 = (blockIdx.x & 31) << 7;

    int px = tid & 127;
    int cg = tid >> 7;           // 0..3: 16-channel group
    int hpx = (px0 + px) >> 6;   // this pixel's row
    int wpx = (px0 + px) & 63;

    // ================= PHASE 1: offset conv GEMM (D_off[32][128]) ==========
    float acc1[2][4];
#pragma unroll
    for (int mi = 0; mi < 2; ++mi)
#pragma unroll
        for (int q = 0; q < 4; ++q) acc1[mi][q] = 0.f;

    for (int kb = 0; kb < 36; ++kb) {
        int kk = kb >> 2;
        if (kb) __syncthreads();

        // stage A_off hi/lo: 32 rows x 64 ck (4KB each)
        if (tid < 256) {
            const uint4* ah = (const uint4*)(owhi + ((size_t)kb << 11));
            const uint4* al = (const uint4*)(owlo + ((size_t)kb << 11));
            int row = tid >> 3, seg = tid & 7;
            uint32_t o = ((uint32_t)row << 7) + (((uint32_t)seg << 4) ^ ((row & 7) << 4));
            *(uint4*)(smem + SM_A + o) = ah[tid];
            *(uint4*)(smem + SM_ALO + o) = al[tid];
        }

        // stage B im2col: [128 px][64 ck], tap kk, c-block kb&3
        {
            int hh = hpx + kk / 3 - 1;
            int ww = wpx + kk % 3 - 1;
            bool valid = (hh >= 0) && (hh < 64) && (ww >= 0) && (ww < 64);
            int src = valid ? hh * 64 + ww : 0;
            const float* xb = x + ((size_t)(b * 256) + ((kb & 3) << 6) + (cg << 4)) * HWSZ + src;
            uint32_t hp[8], lp[8];
#pragma unroll
            for (int jj = 0; jj < 8; ++jj) {
                float v0 = valid ? xb[(size_t)(jj << 1) * HWSZ] : 0.f;
                float v1 = valid ? xb[(size_t)((jj << 1) + 1) * HWSZ] : 0.f;
                __nv_bfloat162 h2, l2;
                h2.x = __float2bfloat16_rn(v0);
                h2.y = __float2bfloat16_rn(v1);
                l2.x = __float2bfloat16_rn(v0 - __bfloat162float(h2.x));
                l2.y = __float2bfloat16_rn(v1 - __bfloat162float(h2.y));
                hp[jj] = *(uint32_t*)&h2;
                lp[jj] = *(uint32_t*)&l2;
            }
            uint32_t rb = (uint32_t)px << 7;
            uint32_t xm = ((uint32_t)px & 7) << 4;
            uint32_t c0b = (uint32_t)cg << 5;
            uint32_t o0 = rb + (c0b ^ xm);
            uint32_t o1 = rb + ((c0b + 16) ^ xm);
            *(uint4*)(smem + SM_BHI + o0) = make_uint4(hp[0], hp[1], hp[2], hp[3]);
            *(uint4*)(smem + SM_BHI + o1) = make_uint4(hp[4], hp[5], hp[6], hp[7]);
            *(uint4*)(smem + SM_BLO + o0) = make_uint4(lp[0], lp[1], lp[2], lp[3]);
            *(uint4*)(smem + SM_BLO + o1) = make_uint4(lp[4], lp[5], lp[6], lp[7]);
        }
        __syncthreads();

        // mma: warp wid covers n8 col = wid*8, two m16 halves
        int n_base = wid << 3;
#pragma unroll
        for (int ks = 0; ks < 4; ++ks) {
            uint32_t ah1[2][4], al1[2][4], bh1[2], bl1[2];
#pragma unroll
            for (int mi = 0; mi < 2; ++mi) {
                int row = (mi << 4) + (lane & 15);
                uint32_t o = ((uint32_t)row << 7) +
                             ((uint32_t)((ks << 5) + ((lane >> 4) << 4)) ^ ((row & 7) << 4));
                LDSM4(ah1[mi], sb + SM_A + o);
                LDSM4(al1[mi], sb + SM_ALO + o);
            }
            int brow = n_base + (lane & 7);
            uint32_t bo = ((uint32_t)brow << 7) +
                          ((uint32_t)((ks << 5) + (((lane >> 3) & 1) << 4)) ^ ((brow & 7) << 4));
            LDSM2(bh1, sb + SM_BHI + bo);
            LDSM2(bl1, sb + SM_BLO + bo);
#pragma unroll
            for (int mi = 0; mi < 2; ++mi) {
                MMA16816(acc1[mi], ah1[mi], bh1[0], bh1[1]);
                MMA16816(acc1[mi], al1[mi], bh1[0], bh1[1]);
                MMA16816(acc1[mi], ah1[mi], bl1[0], bl1[1]);
            }
        }
    }
    __syncthreads();

    // write offsets to smem (reuse SM_BHI region): offs[32][128] f32
    {
        float* offs = (float*)(smem + SM_BHI);
#pragma unroll
        for (int mi = 0; mi < 2; ++mi) {
            int ocp = (mi << 4) + (lane >> 2);
            int pc = (wid << 3) + ((lane & 3) << 1);
            offs[ocp * 128 + pc] = acc1[mi][0];
            offs[ocp * 128 + pc + 1] = acc1[mi][1];
            offs[(ocp + 8) * 128 + pc] = acc1[mi][2];
            offs[(ocp + 8) * 128 + pc + 1] = acc1[mi][3];
        }
    }
    __syncthreads();

    // ---- bilinear metadata from smem offsets ----
    int* midx = (int*)(smem + SM_MIDX);
    float* mwgt = (float*)(smem + SM_MW);
    {
        const float* offs = (const float*)(smem + SM_BHI);
        for (int i = tid; i < 1152; i += 512) {
            int kk = i >> 7;
            int p = i & 127;
            int pix = px0 + p;
            int h = pix >> 6;
            int w = pix & 63;
            float dy = offs[((2 * kk) << 7) + p] + offbias[2 * kk];
            float dx = offs[((2 * kk + 1) << 7) + p] + offbias[2 * kk + 1];
            float py = (float)(h + kk / 3 - 1) + dy;
            float px_ = (float)(w + kk % 3 - 1) + dx;
            float y0f = floorf(py), x0f = floorf(px_);
            int y0 = (int)y0f, x0 = (int)x0f;
            float wy = py - y0f, wx = px_ - x0f;
            float cw[4];
            int cy[4], cx[4];
            cw[0] = (1.f - wy) * (1.f - wx); cy[0] = y0;     cx[0] = x0;
            cw[1] = (1.f - wy) * wx;         cy[1] = y0;     cx[1] = x0 + 1;
            cw[2] = wy * (1.f - wx);         cy[2] = y0 + 1; cx[2] = x0;
            cw[3] = wy * wx;                 cy[3] = y0 + 1; cx[3] = x0 + 1;
#pragma unroll
            for (int q = 0; q < 4; ++q) {
                bool valid = (cy[q] >= 0) && (cy[q] < 64) && (cx[q] >= 0) && (cx[q] < 64);
                int yy = cy[q] < 0 ? 0 : (cy[q] > 63 ? 63 : cy[q]);
                int xx = cx[q] < 0 ? 0 : (cx[q] > 63 ? 63 : cx[q]);
                midx[i * 4 + q] = yy * 64 + xx;
                mwgt[i * 4 + q] = valid ? cw[q] : 0.f;
            }
        }
    }
    __syncthreads();

    // ================= PHASE 2: deform GEMM (D[256][128]) ==================
    float acc[4][4][4];
#pragma unroll
    for (int mi = 0; mi < 4; ++mi)
#pragma unroll
        for (int nj = 0; nj < 4; ++nj)
#pragma unroll
            for (int q = 0; q < 4; ++q) acc[mi][nj][q] = 0.f;

    int m_base = (wid & 3) << 6;
    int n_base = (wid >> 2) << 5;

    for (int kb = 0; kb < 36; ++kb) {
        int kk = kb >> 2;
        if (kb) __syncthreads();

        // stage A (weights) hi/lo: [256 oc][64 ck] swizzled
        {
            const uint4* ah = (const uint4*)(whi + ((size_t)kb << 14));
            const uint4* al = (const uint4*)(wlo + ((size_t)kb << 14));
#pragma unroll
            for (int t = 0; t < 4; ++t) {
                int i = tid + (t << 9);
                int row = i >> 3, seg = i & 7;
                uint32_t o = ((uint32_t)row << 7) + (((uint32_t)seg << 4) ^ ((row & 7) << 4));
                *(uint4*)(smem + SM_A + o) = ah[i];
                *(uint4*)(smem + SM_ALO + o) = al[i];
            }
        }

        // sample B tile: [128 px][64 ck] tap kk
        {
            const int* mi_ = &midx[(kk * 128 + px) * 4];
            const float* mw_ = &mwgt[(kk * 128 + px) * 4];
            int i0 = mi_[0], i1 = mi_[1], i2 = mi_[2], i3 = mi_[3];
            float w0 = mw_[0], w1 = mw_[1], w2 = mw_[2], w3 = mw_[3];
            const float* xb = x + ((size_t)(b * 256) + ((kb & 3) << 6) + (cg << 4)) * HWSZ;
            uint32_t hp[8], lp[8];
#pragma unroll
            for (int jj = 0; jj < 8; ++jj) {
                const float* p0 = xb + (size_t)(jj << 1) * HWSZ;
                const float* p1 = p0 + HWSZ;
                float v0 = fmaf(w3, p0[i3], fmaf(w2, p0[i2], fmaf(w1, p0[i1], w0 * p0[i0])));
                float v1 = fmaf(w3, p1[i3], fmaf(w2, p1[i2], fmaf(w1, p1[i1], w0 * p1[i0])));
                __nv_bfloat162 h2, l2;
                h2.x = __float2bfloat16_rn(v0);
                h2.y = __float2bfloat16_rn(v1);
                l2.x = __float2bfloat16_rn(v0 - __bfloat162float(h2.x));
                l2.y = __float2bfloat16_rn(v1 - __bfloat162float(h2.y));
                hp[jj] = *(uint32_t*)&h2;
                lp[jj] = *(uint32_t*)&l2;
            }
            uint32_t rb = (uint32_t)px << 7;
            uint32_t xm = ((uint32_t)px & 7) << 4;
            uint32_t c0b = (uint32_t)cg << 5;
            uint32_t o0 = rb + (c0b ^ xm);
            uint32_t o1 = rb + ((c0b + 16) ^ xm);
            *(uint4*)(smem + SM_BHI + o0) = make_uint4(hp[0], hp[1], hp[2], hp[3]);
            *(uint4*)(smem + SM_BHI + o1) = make_uint4(hp[4], hp[5], hp[6], hp[7]);
            *(uint4*)(smem + SM_BLO + o0) = make_uint4(lp[0], lp[1], lp[2], lp[3]);
            *(uint4*)(smem + SM_BLO + o1) = make_uint4(lp[4], lp[5], lp[6], lp[7]);
        }
        __syncthreads();

        // ldmatrix + mma: 4 k16-steps
#pragma unroll
        for (int ks = 0; ks < 4; ++ks) {
            uint32_t ah_[4][4], al_[4][4], bf[2][4];
            int arow0 = m_base + (lane & 15);
            uint32_t acolb = (uint32_t)((ks << 5) + ((lane >> 4) << 4));
#pragma unroll
            for (int mi = 0; mi < 4; ++mi) {
                int row = arow0 + (mi << 4);
                uint32_t o = ((uint32_t)row << 7) + (acolb ^ ((row & 7) << 4));
                LDSM4(ah_[mi], sb + SM_A + o);
                LDSM4(al_[mi], sb + SM_ALO + o);
            }
            int brow0 = n_base + ((lane >> 4) << 3) + (lane & 7);
            uint32_t bcolb = (uint32_t)((ks << 5) + (((lane >> 3) & 1) << 4));
#pragma unroll
            for (int np = 0; np < 2; ++np) {
                int row = brow0 + (np << 4);
                uint32_t o = ((uint32_t)row << 7) + (bcolb ^ ((row & 7) << 4));
                LDSM4(bf[np], sb + SM_BHI + o);
            }
#pragma unroll
            for (int mi = 0; mi < 4; ++mi)
#pragma unroll
                for (int nj = 0; nj < 4; ++nj) {
                    MMA16816(acc[mi][nj], ah_[mi], bf[nj >> 1][(nj & 1) * 2], bf[nj >> 1][(nj & 1) * 2 + 1]);
                    MMA16816(acc[mi][nj], al_[mi], bf[nj >> 1][(nj & 1) * 2], bf[nj >> 1][(nj & 1) * 2 + 1]);
                }
#pragma unroll
            for (int np = 0; np < 2; ++np) {
                int row = brow0 + (np << 4);
                uint32_t o = ((uint32_t)row << 7) + (bcolb ^ ((row & 7) << 4));
                LDSM4(bf[np], sb + SM_BLO + o);
            }
#pragma unroll
            for (int mi = 0; mi < 4; ++mi)
#pragma unroll
                for (int nj = 0; nj < 4; ++nj)
                    MMA16816(acc[mi][nj], ah_[mi], bf[nj >> 1][(nj & 1) * 2], bf[nj >> 1][(nj & 1) * 2 + 1]);
        }
    }

    // ---- epilogue: relu + direct v2 stores ----
    float* outb = out + (size_t)b * CC * HWSZ + px0;
#pragma unroll
    for (int mi = 0; mi < 4; ++mi) {
#pragma unroll
        for (int nj = 0; nj < 4; ++nj) {
            int row = m_base + (mi << 4) + (lane >> 2);
            int colp = n_base + (nj << 3) + ((lane & 3) << 1);
            float2 v0, v1;
            v0.x = fmaxf(acc[mi][nj][0], 0.f);
            v0.y = fmaxf(acc[mi][nj][1], 0.f);
            v1.x = fmaxf(acc[mi][nj][2], 0.f);
            v1.y = fmaxf(acc[mi][nj][3], 0.f);
            *(float2*)(outb + (size_t)row * HWSZ + colp) = v0;
            *(float2*)(outb + (size_t)(row + 8) * HWSZ + colp) = v1;
        }
    }
}

// ---------------- launch ----------------------------------------------------
extern "C" void kernel_launch(void* const* d_in, const int* in_sizes, int n_in,
                              void* d_out, int out_size) {
    (void)in_sizes; (void)n_in; (void)out_size;
    const float* x    = (const float*)d_in[0];
    const float* offw = (const float*)d_in[1];
    const float* offb = (const float*)d_in[2];
    const float* w    = (const float*)d_in[3];
    float* out = (float*)d_out;

    float *bufA, *bufB;
    __nv_bfloat16 *gwhi, *gwlo, *gowhi, *gowlo;
    cudaGetSymbolAddress((void**)&bufA, g_bufA);
    cudaGetSymbolAddress((void**)&bufB, g_bufB);
    cudaGetSymbolAddress((void**)&gwhi, g_whi);
    cudaGetSymbolAddress((void**)&gwlo, g_wlo);
    cudaGetSymbolAddress((void**)&gowhi, g_owhi);
    cudaGetSymbolAddress((void**)&gowlo, g_owlo);

    cudaFuncSetAttribute(fused_layer_kernel,
                         cudaFuncAttributeMaxDynamicSharedMemorySize, SM_TOTAL);

    prep_w_kernel<<<(2359296 + 255) / 256, 256>>>(w, gwhi, gwlo);
    prep_offw_kernel<<<(294912 + 255) / 256, 256>>>(offw, gowhi, gowlo);

    const float* cur = x;
    for (int r = 0; r < RB; ++r) {
        float* nxt = (r == 3) ? out : ((r & 1) == 0 ? bufA : bufB);
        fused_layer_kernel<<<128, 512, SM_TOTAL>>>(
            cur, gowhi + (size_t)r * 73728, gowlo + (size_t)r * 73728,
            offb + r * OC2, gwhi + (size_t)r * 589824, gwlo + (size_t)r * 589824, nxt);
        cur = nxt;
    }
}